// round 6
// baseline (speedup 1.0000x reference)
#include <cuda_runtime.h>
#include <math.h>

#define NCLS 80
#define MAXT 64
#define GRID 256
#define TPB  512

__constant__ float c_aw[9] = {10.f,16.f,33.f,30.f,62.f,59.f,116.f,156.f,373.f};
__constant__ float c_ah[9] = {13.f,30.f,23.f,61.f,45.f,119.f,90.f,198.f,326.f};

__device__ double g_acc = 0.0;
__device__ unsigned int g_count = 0;

// exact-ish sigmoid for sparse sites (few of them)
__device__ __forceinline__ float sigf(float x)   { return 1.0f / (1.0f + __expf(-x)); }
// dense sigmoid^2 via single-MUFU tanh.approx: sigmoid(x) = 0.5*(1+tanh(x/2))
__device__ __forceinline__ float sq_sig(float x) {
    float t;
    asm("tanh.approx.f32 %0, %1;" : "=f"(t) : "f"(x * 0.5f));
    float s = fmaf(0.5f, t, 0.5f);
    return s * s;
}
// -log(sigmoid(x)) = softplus(-x);  -log1p(-sigmoid(x)) = softplus(x)
__device__ __forceinline__ float softplusf(float x) { return __logf(1.0f + __expf(x)); }

// all-float block reduce for 512 threads; result valid on thread 0
__device__ __forceinline__ float blockReduceF(float v) {
    __shared__ float sw[16];
    int lane = threadIdx.x & 31;
    int wid  = threadIdx.x >> 5;
    #pragma unroll
    for (int o = 16; o > 0; o >>= 1)
        v += __shfl_down_sync(0xffffffffu, v, o);
    if (lane == 0) sw[wid] = v;
    __syncthreads();
    if (wid == 0) {
        v = (lane < 16) ? sw[lane] : 0.0f;
        #pragma unroll
        for (int o = 8; o > 0; o >>= 1)
            v += __shfl_down_sync(0xffffffffu, v, o);
    }
    return v;
}

__global__ void __launch_bounds__(TPB) yolo_fused(
                           const float* __restrict__ p3,
                           const float* __restrict__ p4,
                           const float* __restrict__ p5,
                           const float* __restrict__ tgt,
                           float* __restrict__ out,
                           int B, int T)
{
    float facc = 0.0f;

    if ((int)blockIdx.x >= B) {
        // ================= dense: sum sigmoid(conf)^2 over all cells ==========
        const int tid = (blockIdx.x - B) * TPB + threadIdx.x;
        const int nth = (gridDim.x - B) * TPB;
        {   // p3: 2704 floats/plane -> 676 float4
            const int PF4 = 676, tot = B * 3 * PF4;
            #pragma unroll 2
            for (int e = tid; e < tot; e += nth) {
                int plane = e / PF4, off = e - plane * PF4;
                int b = plane / 3, a = plane - b * 3;
                const float4* pl = (const float4*)(p3 + ((size_t)b * 255 + a * 85 + 4) * 2704);
                float4 v = pl[off];
                facc += sq_sig(v.x) + sq_sig(v.y) + sq_sig(v.z) + sq_sig(v.w);
            }
        }
        {   // p4: 676 floats/plane -> 169 float4
            const int PF4 = 169, tot = B * 3 * PF4;
            for (int e = tid; e < tot; e += nth) {
                int plane = e / PF4, off = e - plane * PF4;
                int b = plane / 3, a = plane - b * 3;
                const float4* pl = (const float4*)(p4 + ((size_t)b * 255 + a * 85 + 4) * 676);
                float4 v = pl[off];
                facc += sq_sig(v.x) + sq_sig(v.y) + sq_sig(v.z) + sq_sig(v.w);
            }
        }
        {   // p5: 169 scalar/plane
            const int PH = 169, tot = B * 3 * PH;
            for (int e = tid; e < tot; e += nth) {
                int plane = e / PH, off = e - plane * PH;
                int b = plane / 3, a = plane - b * 3;
                facc += sq_sig(p5[((size_t)b * 255 + a * 85 + 4) * 169 + off]);
            }
        }
    } else {
        // ================= sparse: per-batch annotations =======================
        __shared__ int   s_key[MAXT];    // packed (layer,bl,gj,gi), -1 invalid
        __shared__ int   s_cell[MAXT];   // packed (layer,gj,gi),    -1 invalid
        __shared__ int   s_nzm[MAXT];    // 3-bit: iou_local[a] > 0.5
        __shared__ int   s_cid[MAXT];
        __shared__ float s_tx[MAXT], s_ty[MAXT], s_tw[MAXT], s_th[MAXT];
        __shared__ int   s_n;
        __shared__ const float* s_optr[MAXT];  // owner: &p[(b*255+bl*85+5)*HW + pos]
        __shared__ int   s_ohw[MAXT];
        __shared__ unsigned s_om[MAXT * 3];

        const int b = blockIdx.x;
        const int t = threadIdx.x;

        if (t == 0) s_n = 0;
        if (t < MAXT) { s_key[t] = -1; s_cell[t] = -1; s_nzm[t] = 0; }

        if (t < T) {
            const float* an = tgt + ((size_t)b * T + t) * 5;
            float a0 = an[0], a1 = an[1], a2 = an[2], a3 = an[3], a4 = an[4];
            bool valid = (a0 + a1 + a2 + a3 + a4) > 0.0f;
            float gwp = a2 * 416.0f, ghp = a3 * 416.0f;
            float iou[9];
            float best = -1.0f; int bn = 0;
            #pragma unroll
            for (int k = 0; k < 9; k++) {
                float inter = fminf(gwp, c_aw[k]) * fminf(ghp, c_ah[k]);
                float uni   = gwp * ghp + c_aw[k] * c_ah[k] - inter;
                float v     = inter / (uni + 1e-16f);
                iou[k] = v;
                if (v > best) { best = v; bn = k; }   // first max wins (jnp.argmax)
            }
            int layer = bn / 3;
            int W = (layer == 0) ? 52 : ((layer == 1) ? 26 : 13);
            float Wf = (float)W;
            float gx = a0 * Wf, gy = a1 * Wf;
            int gi = min(max((int)gx, 0), W - 1);
            int gj = min(max((int)gy, 0), W - 1);
            float scale = Wf / 416.0f;
            s_tx[t] = gx - (float)gi;
            s_ty[t] = gy - (float)gj;
            s_tw[t] = (a2 * Wf) / (c_aw[bn] * scale);
            s_th[t] = (a3 * Wf) / (c_ah[bn] * scale);
            s_cid[t] = min(max((int)a4, 0), NCLS - 1);
            if (valid) {
                int bl = bn - 3 * layer;
                s_key[t]  = (layer << 18) | (bl << 16) | (gj << 8) | gi;
                s_cell[t] = (layer << 16) | (gj << 8) | gi;
                int m = 0;
                #pragma unroll
                for (int a = 0; a < 3; a++)
                    m |= (iou[3 * layer + a] > 0.5f) ? (1 << a) : 0;
                s_nzm[t] = m;
            }
        }
        __syncthreads();

        // ---- noobj zeroed-cell subtraction: one (ti, a) item per thread -------
        {
            int ti = t >> 2;
            int a  = t & 3;
            if (ti < MAXT && a < 3) {
                int cell = s_cell[ti];
                if (cell >= 0 && ((s_nzm[ti] >> a) & 1)) {
                    bool first = true;
                    #pragma unroll 16
                    for (int u = 0; u < ti; u++)
                        first &= !((s_cell[u] == cell) && ((s_nzm[u] >> a) & 1));
                    if (first) {
                        int L = cell >> 16, gj = (cell >> 8) & 0xff, gi = cell & 0xff;
                        int W = (L == 0) ? 52 : ((L == 1) ? 26 : 13);
                        int HW = W * W;
                        const float* p = (L == 0) ? p3 : ((L == 1) ? p4 : p5);
                        float x = p[((size_t)b * 255 + a * 85 + 4) * HW + (gj * W + gi)];
                        facc -= sq_sig(x);   // same approx as dense -> cancels exactly
                    }
                }
            }
        }

        // ---- owner resolution + class-union mask + box/obj loss ---------------
        if (t < MAXT) {
            int key = s_key[t];
            if (key >= 0) {
                bool owner = true;
                #pragma unroll 16
                for (int u = t + 1; u < MAXT; u++)
                    owner &= (s_key[u] != key);
                if (owner) {
                    unsigned m0 = 0, m1 = 0, m2 = 0;
                    #pragma unroll 16
                    for (int u = 0; u < MAXT; u++) {
                        if (s_key[u] == key) {
                            int c = s_cid[u];
                            if (c < 32)      m0 |= 1u << c;
                            else if (c < 64) m1 |= 1u << (c - 32);
                            else             m2 |= 1u << (c - 64);
                        }
                    }
                    int L = key >> 18, bl = (key >> 16) & 3;
                    int gj = (key >> 8) & 0xff, gi = key & 0xff;
                    int W = (L == 0) ? 52 : ((L == 1) ? 26 : 13);
                    int HW = W * W;
                    const float* p = (L == 0) ? p3 : ((L == 1) ? p4 : p5);
                    size_t base = ((size_t)b * 255 + bl * 85) * HW + (gj * W + gi);
                    float x0 = p[base];
                    float x1 = p[base + HW];
                    float x2 = p[base + 2 * (size_t)HW];
                    float x3 = p[base + 3 * (size_t)HW];
                    float x4 = p[base + 4 * (size_t)HW];
                    float dx = sigf(x0) - s_tx[t], dy = sigf(x1) - s_ty[t];
                    float dw = __expf(x2) - s_tw[t], dh = __expf(x3) - s_th[t];
                    facc += dx * dx + dy * dy + dw * dw + dh * dh;   // LAMBDA_COORD=1
                    float dc = sigf(x4) - 1.0f;
                    facc += 5.0f * dc * dc;                          // LAMBDA_OBJ=5

                    int slot = atomicAdd(&s_n, 1);
                    s_optr[slot] = p + base + 5 * (size_t)HW;
                    s_ohw[slot]  = HW;
                    s_om[slot * 3 + 0] = m0;
                    s_om[slot * 3 + 1] = m1;
                    s_om[slot * 3 + 2] = m2;
                }
            }
        }
        __syncthreads();

        // ---- class BCE over compact owner list (guard-free, const-div 80) -----
        {
            int nItems = s_n * NCLS;
            #pragma unroll 4
            for (int idx = t; idx < nItems; idx += TPB) {
                int o = idx / NCLS;
                int c = idx - o * NCLS;
                const float* ptr = s_optr[o];
                float x = ptr[(size_t)c * s_ohw[o]];
                unsigned w = s_om[o * 3 + (c >> 5)];
                bool tc = (w >> (c & 31)) & 1u;
                float l = softplusf(tc ? -x : x);
                facc += fminf(l, 100.0f);
            }
        }
        __syncthreads();
    }

    // ================= block partial -> single global double ====================
    float bsum = blockReduceF(facc);

    if (threadIdx.x == 0) {
        atomicAdd(&g_acc, (double)bsum);
        __threadfence();
        unsigned int old = atomicAdd(&g_count, 1u);
        if (old == gridDim.x - 1) {
            out[0] = (float)(g_acc / (double)B);
            g_acc = 0.0;      // reset for next graph replay
            g_count = 0;
        }
    }
}

extern "C" void kernel_launch(void* const* d_in, const int* in_sizes, int n_in,
                              void* d_out, int out_size)
{
    const float* p3  = (const float*)d_in[0];
    const float* p4  = (const float*)d_in[1];
    const float* p5  = (const float*)d_in[2];
    const float* tgt = (const float*)d_in[3];

    int B = in_sizes[0] / (255 * 52 * 52);
    int T = in_sizes[3] / (B * 5);
    if (T > MAXT) T = MAXT;

    yolo_fused<<<GRID, TPB>>>(p3, p4, p5, tgt, (float*)d_out, B, T);
}

// round 7
// speedup vs baseline: 1.0151x; 1.0151x over previous
#include <cuda_runtime.h>
#include <math.h>

#define NCLS 80
#define MAXT 64
#define TPB  512
#define DENSE_BLOCKS 32
#define MAXGRID 256

__constant__ float c_aw[9] = {10.f,16.f,33.f,30.f,62.f,59.f,116.f,156.f,373.f};
__constant__ float c_ah[9] = {13.f,30.f,23.f,61.f,45.f,119.f,90.f,198.f,326.f};

__device__ float g_part[MAXGRID];
__device__ unsigned int g_count = 0;

// exact-ish sigmoid for sparse sites (few of them)
__device__ __forceinline__ float sigf(float x)   { return 1.0f / (1.0f + __expf(-x)); }
// dense sigmoid^2 via single-MUFU tanh.approx: sigmoid(x) = 0.5*(1+tanh(x/2))
__device__ __forceinline__ float sq_sig(float x) {
    float t;
    asm("tanh.approx.f32 %0, %1;" : "=f"(t) : "f"(x * 0.5f));
    float s = fmaf(0.5f, t, 0.5f);
    return s * s;
}
// -log(sigmoid(x)) = softplus(-x);  -log1p(-sigmoid(x)) = softplus(x)
__device__ __forceinline__ float softplusf(float x) { return __logf(1.0f + __expf(x)); }

// all-float block reduce for 512 threads; result valid on thread 0
__device__ __forceinline__ float blockReduceF(float v) {
    __shared__ float sw[16];
    int lane = threadIdx.x & 31;
    int wid  = threadIdx.x >> 5;
    #pragma unroll
    for (int o = 16; o > 0; o >>= 1)
        v += __shfl_down_sync(0xffffffffu, v, o);
    if (lane == 0) sw[wid] = v;
    __syncthreads();
    if (wid == 0) {
        v = (lane < 16) ? sw[lane] : 0.0f;
        #pragma unroll
        for (int o = 8; o > 0; o >>= 1)
            v += __shfl_down_sync(0xffffffffu, v, o);
    }
    return v;
}

__global__ void __launch_bounds__(TPB) yolo_fused(
                           const float* __restrict__ p3,
                           const float* __restrict__ p4,
                           const float* __restrict__ p5,
                           const float* __restrict__ tgt,
                           float* __restrict__ out,
                           int B, int T)
{
    float facc = 0.0f;

    if ((int)blockIdx.x >= B) {
        // ================= dense: sum sigmoid(conf)^2 over all cells ==========
        const int tid = (blockIdx.x - B) * TPB + threadIdx.x;
        const int nth = (gridDim.x - B) * TPB;
        {   // p3: 2704 floats/plane -> 676 float4
            const int PF4 = 676, tot = B * 3 * PF4;
            #pragma unroll 4
            for (int e = tid; e < tot; e += nth) {
                int plane = e / PF4, off = e - plane * PF4;
                int b = plane / 3, a = plane - b * 3;
                const float4* pl = (const float4*)(p3 + ((size_t)b * 255 + a * 85 + 4) * 2704);
                float4 v = pl[off];
                facc += sq_sig(v.x) + sq_sig(v.y) + sq_sig(v.z) + sq_sig(v.w);
            }
        }
        {   // p4: 676 floats/plane -> 169 float4
            const int PF4 = 169, tot = B * 3 * PF4;
            for (int e = tid; e < tot; e += nth) {
                int plane = e / PF4, off = e - plane * PF4;
                int b = plane / 3, a = plane - b * 3;
                const float4* pl = (const float4*)(p4 + ((size_t)b * 255 + a * 85 + 4) * 676);
                float4 v = pl[off];
                facc += sq_sig(v.x) + sq_sig(v.y) + sq_sig(v.z) + sq_sig(v.w);
            }
        }
        {   // p5: 169 scalar/plane
            const int PH = 169, tot = B * 3 * PH;
            for (int e = tid; e < tot; e += nth) {
                int plane = e / PH, off = e - plane * PH;
                int b = plane / 3, a = plane - b * 3;
                facc += sq_sig(p5[((size_t)b * 255 + a * 85 + 4) * 169 + off]);
            }
        }
    } else {
        // ================= sparse: per-batch annotations =======================
        __shared__ int   s_key[MAXT];    // packed (layer,bl,gj,gi), -1 invalid
        __shared__ int   s_cell[MAXT];   // packed (layer,gj,gi),    -1 invalid
        __shared__ int   s_nzm[MAXT];    // 3-bit: iou_local[a] > 0.5
        __shared__ int   s_cid[MAXT];
        __shared__ float s_tx[MAXT], s_ty[MAXT], s_tw[MAXT], s_th[MAXT];
        __shared__ int   s_n;
        __shared__ const float* s_optr[MAXT];  // owner: &p[(b*255+bl*85+5)*HW + pos]
        __shared__ int   s_ohw[MAXT];
        __shared__ unsigned s_om[MAXT * 3];

        const int b = blockIdx.x;
        const int t = threadIdx.x;

        if (t == 0) s_n = 0;
        if (t < MAXT) { s_key[t] = -1; s_cell[t] = -1; s_nzm[t] = 0; }

        if (t < T) {
            const float* an = tgt + ((size_t)b * T + t) * 5;
            float a0 = an[0], a1 = an[1], a2 = an[2], a3 = an[3], a4 = an[4];
            bool valid = (a0 + a1 + a2 + a3 + a4) > 0.0f;
            float gwp = a2 * 416.0f, ghp = a3 * 416.0f;
            float iou[9];
            float best = -1.0f; int bn = 0;
            #pragma unroll
            for (int k = 0; k < 9; k++) {
                float inter = fminf(gwp, c_aw[k]) * fminf(ghp, c_ah[k]);
                float uni   = gwp * ghp + c_aw[k] * c_ah[k] - inter;
                float v     = inter / (uni + 1e-16f);
                iou[k] = v;
                if (v > best) { best = v; bn = k; }   // first max wins (jnp.argmax)
            }
            int layer = bn / 3;
            int W = (layer == 0) ? 52 : ((layer == 1) ? 26 : 13);
            float Wf = (float)W;
            float gx = a0 * Wf, gy = a1 * Wf;
            int gi = min(max((int)gx, 0), W - 1);
            int gj = min(max((int)gy, 0), W - 1);
            float scale = Wf / 416.0f;
            s_tx[t] = gx - (float)gi;
            s_ty[t] = gy - (float)gj;
            s_tw[t] = (a2 * Wf) / (c_aw[bn] * scale);
            s_th[t] = (a3 * Wf) / (c_ah[bn] * scale);
            s_cid[t] = min(max((int)a4, 0), NCLS - 1);
            if (valid) {
                int bl = bn - 3 * layer;
                s_key[t]  = (layer << 18) | (bl << 16) | (gj << 8) | gi;
                s_cell[t] = (layer << 16) | (gj << 8) | gi;
                int m = 0;
                #pragma unroll
                for (int a = 0; a < 3; a++)
                    m |= (iou[3 * layer + a] > 0.5f) ? (1 << a) : 0;
                s_nzm[t] = m;
            }
        }
        __syncthreads();

        // ---- noobj zeroed-cell subtraction: one (ti, a) item per thread -------
        {
            int ti = t >> 2;
            int a  = t & 3;
            if (ti < MAXT && a < 3) {
                int cell = s_cell[ti];
                if (cell >= 0 && ((s_nzm[ti] >> a) & 1)) {
                    bool first = true;
                    #pragma unroll 16
                    for (int u = 0; u < ti; u++)
                        first &= !((s_cell[u] == cell) && ((s_nzm[u] >> a) & 1));
                    if (first) {
                        int L = cell >> 16, gj = (cell >> 8) & 0xff, gi = cell & 0xff;
                        int W = (L == 0) ? 52 : ((L == 1) ? 26 : 13);
                        int HW = W * W;
                        const float* p = (L == 0) ? p3 : ((L == 1) ? p4 : p5);
                        float x = p[((size_t)b * 255 + a * 85 + 4) * HW + (gj * W + gi)];
                        facc -= sq_sig(x);   // same approx as dense -> cancels exactly
                    }
                }
            }
        }

        // ---- owner resolution + class-union mask + box/obj loss ---------------
        if (t < MAXT) {
            int key = s_key[t];
            if (key >= 0) {
                bool owner = true;
                #pragma unroll 16
                for (int u = t + 1; u < MAXT; u++)
                    owner &= (s_key[u] != key);
                if (owner) {
                    unsigned m0 = 0, m1 = 0, m2 = 0;
                    #pragma unroll 16
                    for (int u = 0; u < MAXT; u++) {
                        if (s_key[u] == key) {
                            int c = s_cid[u];
                            if (c < 32)      m0 |= 1u << c;
                            else if (c < 64) m1 |= 1u << (c - 32);
                            else             m2 |= 1u << (c - 64);
                        }
                    }
                    int L = key >> 18, bl = (key >> 16) & 3;
                    int gj = (key >> 8) & 0xff, gi = key & 0xff;
                    int W = (L == 0) ? 52 : ((L == 1) ? 26 : 13);
                    int HW = W * W;
                    const float* p = (L == 0) ? p3 : ((L == 1) ? p4 : p5);
                    size_t base = ((size_t)b * 255 + bl * 85) * HW + (gj * W + gi);
                    float x0 = p[base];
                    float x1 = p[base + HW];
                    float x2 = p[base + 2 * (size_t)HW];
                    float x3 = p[base + 3 * (size_t)HW];
                    float x4 = p[base + 4 * (size_t)HW];
                    float dx = sigf(x0) - s_tx[t], dy = sigf(x1) - s_ty[t];
                    float dw = __expf(x2) - s_tw[t], dh = __expf(x3) - s_th[t];
                    facc += dx * dx + dy * dy + dw * dw + dh * dh;   // LAMBDA_COORD=1
                    float dc = sigf(x4) - 1.0f;
                    facc += 5.0f * dc * dc;                          // LAMBDA_OBJ=5

                    int slot = atomicAdd(&s_n, 1);
                    s_optr[slot] = p + base + 5 * (size_t)HW;
                    s_ohw[slot]  = HW;
                    s_om[slot * 3 + 0] = m0;
                    s_om[slot * 3 + 1] = m1;
                    s_om[slot * 3 + 2] = m2;
                }
            }
        }
        __syncthreads();

        // ---- class BCE over compact owner list (guard-free, const-div 80) -----
        {
            int nItems = s_n * NCLS;
            #pragma unroll 4
            for (int idx = t; idx < nItems; idx += TPB) {
                int o = idx / NCLS;
                int c = idx - o * NCLS;
                const float* ptr = s_optr[o];
                float x = ptr[(size_t)c * s_ohw[o]];
                unsigned w = s_om[o * 3 + (c >> 5)];
                bool tc = (w >> (c & 31)) & 1u;
                float l = softplusf(tc ? -x : x);
                facc += fminf(l, 100.0f);
            }
        }
        __syncthreads();
    }

    // ===== block partial (plain store) + counter; last block re-reduces =========
    float bsum = blockReduceF(facc);

    __shared__ bool isLast;
    if (threadIdx.x == 0) {
        g_part[blockIdx.x] = bsum;
        __threadfence();
        unsigned int old = atomicAdd(&g_count, 1u);
        isLast = (old == gridDim.x - 1);
    }
    __syncthreads();

    if (isLast) {
        float v = (threadIdx.x < gridDim.x) ? g_part[threadIdx.x] : 0.0f;
        float tot = blockReduceF(v);
        if (threadIdx.x == 0) {
            out[0] = tot / (float)B;
            g_count = 0;   // reset for next graph replay
        }
    }
}

extern "C" void kernel_launch(void* const* d_in, const int* in_sizes, int n_in,
                              void* d_out, int out_size)
{
    const float* p3  = (const float*)d_in[0];
    const float* p4  = (const float*)d_in[1];
    const float* p5  = (const float*)d_in[2];
    const float* tgt = (const float*)d_in[3];

    int B = in_sizes[0] / (255 * 52 * 52);
    int T = in_sizes[3] / (B * 5);
    if (T > MAXT) T = MAXT;

    int grid = B + DENSE_BLOCKS;      // 32 sparse + 32 dense
    if (grid > MAXGRID) grid = MAXGRID;
    yolo_fused<<<grid, TPB>>>(p3, p4, p5, tgt, (float*)d_out, B, T);
}